// round 10
// baseline (speedup 1.0000x reference)
#include <cuda_runtime.h>
#include <cuda_bf16.h>
#include <cuda_fp16.h>
#include <cstdint>

#define MAXN 40000
#define MAXG 64
#define HDIM 128
#define BSTRIDE 64

__device__ __half g_h[MAXN * HDIM];         // h' = (x@W) * dinv[row], fp16
__device__ int   g_cnt[MAXN];               // zero-init; reset by k_fused each run
__device__ int   g_bucket[MAXN * BSTRIDE];  // per-dst edge buckets (src ids)
// W packed for smem staging: word i (i<8192): p=i>>12, kc=(i>>9)&7, ntl=(i>>6)&7,
// j=(i>>3)&7, r=i&7; k=kc*16+(j&3)*2+(j>>2)*8; n=p*64+ntl*8+r; word={W[k][n],W[k+1][n]}
__device__ __align__(16) uint32_t g_wpk_hi[8192];
__device__ __align__(16) uint32_t g_wpk_lo[8192];
__device__ float g_pool_add[MAXG * HDIM];   // zero-init; reset by k_mlp each run
__device__ int   g_pool_max[MAXG * HDIM];   // init by k_scatter_prep / reset by k_mlp
__device__ int   g_count[MAXG];             // zero-init; reset by k_mlp

__device__ __forceinline__ int enc_f(float f) {
    int i = __float_as_int(f);
    return i >= 0 ? i : (i ^ 0x7FFFFFFF);
}
__device__ __forceinline__ float dec_f(int i) {
    int j = i >= 0 ? i : (i ^ 0x7FFFFFFF);
    return __int_as_float(j);
}
__device__ __forceinline__ uint32_t pack_bf(float a, float b) {
    __nv_bfloat162 v = __floats2bfloat162_rn(a, b);
    return *(uint32_t*)&v;
}

__device__ __forceinline__ void mma_bf16(float* d, const uint32_t* a, uint32_t b0, uint32_t b1) {
    asm volatile(
        "mma.sync.aligned.m16n8k16.row.col.f32.bf16.bf16.f32 "
        "{%0,%1,%2,%3}, {%4,%5,%6,%7}, {%8,%9}, {%0,%1,%2,%3};"
        : "+f"(d[0]), "+f"(d[1]), "+f"(d[2]), "+f"(d[3])
        : "r"(a[0]), "r"(a[1]), "r"(a[2]), "r"(a[3]), "r"(b0), "r"(b1));
}

__device__ __forceinline__ void split_pack(float2 v, uint32_t& hi, uint32_t& lo) {
    float h0 = __bfloat162float(__float2bfloat16(v.x));
    float h1 = __bfloat162float(__float2bfloat16(v.y));
    hi = pack_bf(h0, h1);
    lo = pack_bf(v.x - h0, v.y - h1);
}

// add a gathered fp16 row chunk (4 feats) into fp32 acc
__device__ __forceinline__ void acc_row(float4& acc, uint2 raw) {
    float2 lo = __half22float2(*(__half2*)&raw.x);
    float2 hi = __half22float2(*(__half2*)&raw.y);
    acc.x += lo.x; acc.y += lo.y; acc.z += hi.x; acc.w += hi.y;
}

// ---------------- launch 0: W split/pack + bucket scatter + pool_max init ----------------
__global__ __launch_bounds__(256) void k_scatter_prep(const float* __restrict__ W,
                                                      const int* __restrict__ ei, int E, int G) {
    int i = blockIdx.x * 256 + threadIdx.x;
    if (i < 8192) {
        int p   = i >> 12;
        int kc  = (i >> 9) & 7;
        int ntl = (i >> 6) & 7;
        int j   = (i >> 3) & 7;
        int r   = i & 7;
        int k = kc * 16 + (j & 3) * 2 + (j >> 2) * 8;
        int n = p * 64 + ntl * 8 + r;
        float w0 = W[k * 128 + n];
        float w1 = W[(k + 1) * 128 + n];
        float h0 = __bfloat162float(__float2bfloat16(w0));
        float h1 = __bfloat162float(__float2bfloat16(w1));
        g_wpk_hi[i] = pack_bf(h0, h1);
        g_wpk_lo[i] = pack_bf(w0 - h0, w1 - h1);
    }
    if (i < G * HDIM) g_pool_max[i] = (int)0x80000000;
    if (i < E) {
        int src = ei[i];
        int dst = ei[E + i];
        int pos = atomicAdd(&g_cnt[dst], 1);
        g_bucket[dst * BSTRIDE + pos] = src;
    }
}

// ---------------- launch 1: h' = (x @ W) * dinv -> fp16 : mma.sync bf16 3-term ----------------
__global__ __launch_bounds__(256) void k_gemm_mma(const float* __restrict__ X, int N) {
    __shared__ __align__(16) uint32_t sHi[4096];
    __shared__ __align__(16) uint32_t sLo[4096];
    int tid = threadIdx.x;
    int wid = tid >> 5, lane = tid & 31;
    int r = lane >> 2;
    int cq = lane & 3;
    int rowA = blockIdx.x * 256 + wid * 32 + r;

    float dinvA[2], dinvB[2];
#pragma unroll
    for (int m = 0; m < 2; m++) {
        int ra = rowA + m * 16, rb = ra + 8;
        dinvA[m] = (ra < N) ? rsqrtf((float)g_cnt[ra] + 1.0f) : 0.f;
        dinvB[m] = (rb < N) ? rsqrtf((float)g_cnt[rb] + 1.0f) : 0.f;
    }

#pragma unroll 1
    for (int p = 0; p < 2; p++) {
        {
            const uint4* srcH = (const uint4*)(g_wpk_hi + p * 4096);
            const uint4* srcL = (const uint4*)(g_wpk_lo + p * 4096);
            uint4* dH = (uint4*)sHi;
            uint4* dL = (uint4*)sLo;
#pragma unroll
            for (int q = 0; q < 4; q++) {
                dH[tid + q * 256] = srcH[tid + q * 256];
                dL[tid + q * 256] = srcL[tid + q * 256];
            }
        }
        __syncthreads();

        float acc[2][8][4];
#pragma unroll
        for (int m = 0; m < 2; m++)
#pragma unroll
            for (int nt = 0; nt < 8; nt++)
#pragma unroll
                for (int q = 0; q < 4; q++) acc[m][nt][q] = 0.f;

        int off0 = cq * 8 + r;
        int off1 = (cq + 4) * 8 + r;

#pragma unroll 1
        for (int kc = 0; kc < 8; kc++) {
            int k0 = kc * 16 + cq * 2;
            uint32_t ahi[2][4], alo[2][4];
#pragma unroll
            for (int m = 0; m < 2; m++) {
                int ra = rowA + m * 16;
                int rb = ra + 8;
                bool okA = ra < N, okB = rb < N;
                const float* pa = X + (size_t)ra * 128;
                const float* pb = X + (size_t)rb * 128;
                float2 v0 = okA ? *(const float2*)(pa + k0)     : make_float2(0.f, 0.f);
                float2 v1 = okB ? *(const float2*)(pb + k0)     : make_float2(0.f, 0.f);
                float2 v2 = okA ? *(const float2*)(pa + k0 + 8) : make_float2(0.f, 0.f);
                float2 v3 = okB ? *(const float2*)(pb + k0 + 8) : make_float2(0.f, 0.f);
                split_pack(v0, ahi[m][0], alo[m][0]);
                split_pack(v1, ahi[m][1], alo[m][1]);
                split_pack(v2, ahi[m][2], alo[m][2]);
                split_pack(v3, ahi[m][3], alo[m][3]);
            }
            const uint32_t* bH = sHi + kc * 512;
            const uint32_t* bL = sLo + kc * 512;
#pragma unroll
            for (int nt = 0; nt < 8; nt++) {
                uint32_t bh0 = bH[nt * 64 + off0];
                uint32_t bh1 = bH[nt * 64 + off1];
                uint32_t bl0 = bL[nt * 64 + off0];
                uint32_t bl1 = bL[nt * 64 + off1];
#pragma unroll
                for (int m = 0; m < 2; m++) {
                    mma_bf16(acc[m][nt], ahi[m], bh0, bh1);
                    mma_bf16(acc[m][nt], ahi[m], bl0, bl1);
                    mma_bf16(acc[m][nt], alo[m], bh0, bh1);
                }
            }
        }

#pragma unroll
        for (int m = 0; m < 2; m++) {
            int ra = rowA + m * 16;
            int rb = ra + 8;
            bool okA = ra < N, okB = rb < N;
#pragma unroll
            for (int nt = 0; nt < 8; nt++) {
                int col = p * 64 + nt * 8 + cq * 2;
                if (okA) *(__half2*)(g_h + (size_t)ra * 128 + col) =
                    __float22half2_rn(make_float2(acc[m][nt][0] * dinvA[m], acc[m][nt][1] * dinvA[m]));
                if (okB) *(__half2*)(g_h + (size_t)rb * 128 + col) =
                    __float22half2_rn(make_float2(acc[m][nt][2] * dinvB[m], acc[m][nt][3] * dinvB[m]));
            }
        }
        __syncthreads();
    }
}

// ---------------- launch 2: fused bucket aggregate + selfloop + bias + ReLU + LN + pool ----------------
__global__ __launch_bounds__(256) void k_fused(const int* __restrict__ batch,
                                               const float* __restrict__ bgcn,
                                               const float* __restrict__ gamma,
                                               const float* __restrict__ beta,
                                               int N) {
    __shared__ float s_sum[128];
    __shared__ int   s_max[128];
    __shared__ int   s_cnt;
    int node0 = blockIdx.x * 8;
    if (node0 >= N) return;
    int tid = threadIdx.x;
    int wid = tid >> 5, lane = tid & 31;

    int lastnode = min(node0 + 7, N - 1);
    int gid0 = batch[node0];
    bool uniform = (gid0 == batch[lastnode]);

    if (tid < 128) { s_sum[tid] = 0.f; s_max[tid] = (int)0x80000000; }
    if (tid == 0) s_cnt = 0;
    __syncthreads();

    int node = node0 + wid;
    if (node < N) {
        int deg = g_cnt[node];
        if (lane == 0) g_cnt[node] = 0;     // restore for next graph replay
        float dn = rsqrtf((float)deg + 1.0f);
        const int* bk = g_bucket + (size_t)node * BSTRIDE;
        // acc starts with self term h'[node]
        float4 acc = make_float4(0.f, 0.f, 0.f, 0.f);
        acc_row(acc, *(const uint2*)(g_h + (size_t)node * 128 + lane * 4));
        for (int base = 0; base < deg; base += 32) {
            int j = base + lane;
            int s = (j < deg) ? bk[j] : 0;
            int cnt = min(32, deg - base);
            int t = 0;
            for (; t + 4 <= cnt; t += 4) {
                int s0 = __shfl_sync(0xFFFFFFFFu, s, t);
                int s1 = __shfl_sync(0xFFFFFFFFu, s, t + 1);
                int s2 = __shfl_sync(0xFFFFFFFFu, s, t + 2);
                int s3 = __shfl_sync(0xFFFFFFFFu, s, t + 3);
                uint2 A = *(const uint2*)(g_h + (size_t)s0 * 128 + lane * 4);
                uint2 B = *(const uint2*)(g_h + (size_t)s1 * 128 + lane * 4);
                uint2 C = *(const uint2*)(g_h + (size_t)s2 * 128 + lane * 4);
                uint2 D = *(const uint2*)(g_h + (size_t)s3 * 128 + lane * 4);
                acc_row(acc, A);
                acc_row(acc, B);
                acc_row(acc, C);
                acc_row(acc, D);
            }
            for (; t < cnt; t++) {
                int ss = __shfl_sync(0xFFFFFFFFu, s, t);
                acc_row(acc, *(const uint2*)(g_h + (size_t)ss * 128 + lane * 4));
            }
        }
        float4 b4 = *(const float4*)(bgcn + lane * 4);
        float v0 = fmaxf(fmaf(acc.x, dn, b4.x), 0.f);
        float v1 = fmaxf(fmaf(acc.y, dn, b4.y), 0.f);
        float v2 = fmaxf(fmaf(acc.z, dn, b4.z), 0.f);
        float v3 = fmaxf(fmaf(acc.w, dn, b4.w), 0.f);

        float s  = v0 + v1 + v2 + v3;
        float sq = v0 * v0 + v1 * v1 + v2 * v2 + v3 * v3;
#pragma unroll
        for (int o = 16; o; o >>= 1) {
            s  += __shfl_xor_sync(0xFFFFFFFFu, s, o);
            sq += __shfl_xor_sync(0xFFFFFFFFu, sq, o);
        }
        float mean = s * (1.f / 128.f);
        float var  = sq * (1.f / 128.f) - mean * mean;
        float inv  = rsqrtf(var + 1e-5f);
        float4 gm = *(const float4*)(gamma + lane * 4);
        float4 bt = *(const float4*)(beta + lane * 4);
        float y0 = fmaf((v0 - mean) * inv, gm.x, bt.x);
        float y1 = fmaf((v1 - mean) * inv, gm.y, bt.y);
        float y2 = fmaf((v2 - mean) * inv, gm.z, bt.z);
        float y3 = fmaf((v3 - mean) * inv, gm.w, bt.w);

        if (uniform) {
            atomicAdd(&s_sum[lane * 4 + 0], y0);
            atomicAdd(&s_sum[lane * 4 + 1], y1);
            atomicAdd(&s_sum[lane * 4 + 2], y2);
            atomicAdd(&s_sum[lane * 4 + 3], y3);
            atomicMax(&s_max[lane * 4 + 0], enc_f(y0));
            atomicMax(&s_max[lane * 4 + 1], enc_f(y1));
            atomicMax(&s_max[lane * 4 + 2], enc_f(y2));
            atomicMax(&s_max[lane * 4 + 3], enc_f(y3));
            if (lane == 0) atomicAdd(&s_cnt, 1);
        } else {
            int gid = batch[node];
            float* pa = g_pool_add + (size_t)gid * 128 + lane * 4;
            atomicAdd(pa + 0, y0); atomicAdd(pa + 1, y1);
            atomicAdd(pa + 2, y2); atomicAdd(pa + 3, y3);
            int* pm = g_pool_max + (size_t)gid * 128 + lane * 4;
            atomicMax(pm + 0, enc_f(y0)); atomicMax(pm + 1, enc_f(y1));
            atomicMax(pm + 2, enc_f(y2)); atomicMax(pm + 3, enc_f(y3));
            if (lane == 0) atomicAdd(&g_count[gid], 1);
        }
    }
    __syncthreads();
    if (uniform && tid < 128) {
        atomicAdd(&g_pool_add[(size_t)gid0 * 128 + tid], s_sum[tid]);
        atomicMax(&g_pool_max[(size_t)gid0 * 128 + tid], s_max[tid]);
    }
    if (uniform && tid == 0 && s_cnt > 0) atomicAdd(&g_count[gid0], s_cnt);
}

// ---------------- launch 3: MLP head, 1024-thread k-parallel (+ pool state restore) ----------------
__global__ __launch_bounds__(1024) void k_mlp(const float* __restrict__ W1, const float* __restrict__ b1,
                                              const float* __restrict__ W2, const float* __restrict__ b2,
                                              const float* __restrict__ W3, const float* __restrict__ b3,
                                              float* __restrict__ out, int G) {
    __shared__ float sg[384];
    __shared__ float s_part[1024];
    __shared__ float s1[128];
    __shared__ float s2[64];
    int gid = blockIdx.x;
    int tid = threadIdx.x;
    int cnt = g_count[gid];
    float c = fmaxf((float)cnt, 1.f);
    if (tid < 128) {
        float add = g_pool_add[(size_t)gid * 128 + tid];
        float mx  = (cnt > 0) ? dec_f(g_pool_max[(size_t)gid * 128 + tid]) : 0.f;
        sg[tid]       = add / c;
        sg[128 + tid] = add;
        sg[256 + tid] = mx;
        g_pool_add[(size_t)gid * 128 + tid] = 0.f;
        g_pool_max[(size_t)gid * 128 + tid] = (int)0x80000000;
    }
    if (tid == 0) g_count[gid] = 0;
    __syncthreads();

    // ---- layer 1: 384 -> 128, 8-way k split, 4 accumulators ----
    {
        int o = tid & 127;
        int q = tid >> 7;            // 0..7
        int k0 = q * 48;
        float a0 = 0.f, a1 = 0.f, a2 = 0.f, a3 = 0.f;
        const float* w = W1 + o;
#pragma unroll
        for (int k = k0; k < k0 + 48; k += 4) {
            a0 = fmaf(sg[k + 0], w[(size_t)(k + 0) * 128], a0);
            a1 = fmaf(sg[k + 1], w[(size_t)(k + 1) * 128], a1);
            a2 = fmaf(sg[k + 2], w[(size_t)(k + 2) * 128], a2);
            a3 = fmaf(sg[k + 3], w[(size_t)(k + 3) * 128], a3);
        }
        s_part[tid] = (a0 + a1) + (a2 + a3);
    }
    __syncthreads();
    if (tid < 128) {
        float v = b1[tid];
#pragma unroll
        for (int q = 0; q < 8; q++) v += s_part[tid + q * 128];
        s1[tid] = fmaxf(v, 0.f);
    }
    __syncthreads();

    // ---- layer 2: 128 -> 64, 16-way k split ----
    {
        int o = tid & 63;
        int q = tid >> 6;            // 0..15
        int k0 = q * 8;
        float a0 = 0.f, a1 = 0.f;
        const float* w = W2 + o;
#pragma unroll
        for (int k = k0; k < k0 + 8; k += 2) {
            a0 = fmaf(s1[k + 0], w[(size_t)(k + 0) * 64], a0);
            a1 = fmaf(s1[k + 1], w[(size_t)(k + 1) * 64], a1);
        }
        s_part[tid] = a0 + a1;
    }
    __syncthreads();
    if (tid < 64) {
        float v = b2[tid];
#pragma unroll
        for (int q = 0; q < 16; q++) v += s_part[tid + q * 64];
        s2[tid] = fmaxf(v, 0.f);
    }
    __syncthreads();

    // ---- layer 3: 64 -> 10, one warp per output ----
    {
        int w = tid >> 5, lane = tid & 31;
        if (w < 10) {
            float a = s2[lane] * W3[(size_t)lane * 10 + w]
                    + s2[lane + 32] * W3[(size_t)(lane + 32) * 10 + w];
#pragma unroll
            for (int o = 16; o; o >>= 1) a += __shfl_xor_sync(0xFFFFFFFFu, a, o);
            if (lane == 0) out[gid * 10 + w] = a + b3[w];
        }
    }
}

extern "C" void kernel_launch(void* const* d_in, const int* in_sizes, int n_in,
                              void* d_out, int out_size) {
    const float* x     = (const float*)d_in[0];
    const int*   ei    = (const int*)d_in[1];
    const int*   batch = (const int*)d_in[2];
    const float* Wg    = (const float*)d_in[4];
    const float* bg    = (const float*)d_in[5];
    const float* gamma = (const float*)d_in[6];
    const float* beta  = (const float*)d_in[7];
    const float* W1    = (const float*)d_in[8];
    const float* b1    = (const float*)d_in[9];
    const float* W2    = (const float*)d_in[10];
    const float* b2    = (const float*)d_in[11];
    const float* W3    = (const float*)d_in[12];
    const float* b3    = (const float*)d_in[13];
    float* out = (float*)d_out;

    int N = in_sizes[0] / HDIM;
    int E = in_sizes[1] / 2;
    int G = out_size / 10;

    k_scatter_prep<<<(E + 255) / 256, 256>>>(Wg, ei, E, G);
    k_gemm_mma<<<(N + 255) / 256, 256>>>(x, N);
    k_fused<<<(N + 7) / 8, 256>>>(batch, bg, gamma, beta, N);
    k_mlp<<<G, 1024>>>(W1, b1, W2, b2, W3, b3, out, G);
}

// round 11
// speedup vs baseline: 1.1177x; 1.1177x over previous
#include <cuda_runtime.h>
#include <cuda_bf16.h>
#include <cstdint>

#define MAXN 40000
#define MAXG 64
#define HDIM 128
#define BSTRIDE 64

__device__ float g_h[MAXN * HDIM];          // h' = (x@W) * dinv[row]
__device__ int   g_cnt[MAXN];               // zero-init; reset by k_fused each run
__device__ int   g_bucket[MAXN * BSTRIDE];  // per-dst edge buckets (src ids)
// W packed for smem staging: word i (i<8192): p=i>>12, kc=(i>>9)&7, ntl=(i>>6)&7,
// j=(i>>3)&7, r=i&7; k=kc*16+(j&3)*2+(j>>2)*8; n=p*64+ntl*8+r; word={W[k][n],W[k+1][n]}
__device__ __align__(16) uint32_t g_wpk_hi[8192];
__device__ __align__(16) uint32_t g_wpk_lo[8192];
__device__ float g_pool_add[MAXG * HDIM];   // zero-init; reset by k_mlp each run
__device__ int   g_pool_max[MAXG * HDIM];   // init by k_scatter_prep / reset by k_mlp
__device__ int   g_count[MAXG];             // zero-init; reset by k_mlp

__device__ __forceinline__ int enc_f(float f) {
    int i = __float_as_int(f);
    return i >= 0 ? i : (i ^ 0x7FFFFFFF);
}
__device__ __forceinline__ float dec_f(int i) {
    int j = i >= 0 ? i : (i ^ 0x7FFFFFFF);
    return __int_as_float(j);
}
__device__ __forceinline__ uint32_t pack_bf(float a, float b) {
    __nv_bfloat162 v = __floats2bfloat162_rn(a, b);
    return *(uint32_t*)&v;
}

__device__ __forceinline__ void mma_bf16(float* d, const uint32_t* a, uint32_t b0, uint32_t b1) {
    asm volatile(
        "mma.sync.aligned.m16n8k16.row.col.f32.bf16.bf16.f32 "
        "{%0,%1,%2,%3}, {%4,%5,%6,%7}, {%8,%9}, {%0,%1,%2,%3};"
        : "+f"(d[0]), "+f"(d[1]), "+f"(d[2]), "+f"(d[3])
        : "r"(a[0]), "r"(a[1]), "r"(a[2]), "r"(a[3]), "r"(b0), "r"(b1));
}

__device__ __forceinline__ void split_pack(float2 v, uint32_t& hi, uint32_t& lo) {
    float h0 = __bfloat162float(__float2bfloat16(v.x));
    float h1 = __bfloat162float(__float2bfloat16(v.y));
    hi = pack_bf(h0, h1);
    lo = pack_bf(v.x - h0, v.y - h1);
}

// ---------------- launch 0: W split/pack + bucket scatter + pool_max init ----------------
__global__ __launch_bounds__(256) void k_scatter_prep(const float* __restrict__ W,
                                                      const int* __restrict__ ei, int E, int G) {
    int i = blockIdx.x * 256 + threadIdx.x;
    if (i < 8192) {
        int p   = i >> 12;
        int kc  = (i >> 9) & 7;
        int ntl = (i >> 6) & 7;
        int j   = (i >> 3) & 7;
        int r   = i & 7;
        int k = kc * 16 + (j & 3) * 2 + (j >> 2) * 8;
        int n = p * 64 + ntl * 8 + r;
        float w0 = W[k * 128 + n];
        float w1 = W[(k + 1) * 128 + n];
        float h0 = __bfloat162float(__float2bfloat16(w0));
        float h1 = __bfloat162float(__float2bfloat16(w1));
        g_wpk_hi[i] = pack_bf(h0, h1);
        g_wpk_lo[i] = pack_bf(w0 - h0, w1 - h1);
    }
    if (i < G * HDIM) g_pool_max[i] = (int)0x80000000;
    if (i < E) {
        int src = ei[i];
        int dst = ei[E + i];
        int pos = atomicAdd(&g_cnt[dst], 1);
        g_bucket[dst * BSTRIDE + pos] = src;
    }
}

// ---------------- launch 1: h' = (x @ W) * dinv : mma.sync bf16 3-term, B in smem ----------------
__global__ __launch_bounds__(256) void k_gemm_mma(const float* __restrict__ X, int N) {
    __shared__ __align__(16) uint32_t sHi[4096];
    __shared__ __align__(16) uint32_t sLo[4096];
    int tid = threadIdx.x;
    int wid = tid >> 5, lane = tid & 31;
    int r = lane >> 2;
    int cq = lane & 3;
    int rowA = blockIdx.x * 256 + wid * 32 + r;

    float dinvA[2], dinvB[2];
#pragma unroll
    for (int m = 0; m < 2; m++) {
        int ra = rowA + m * 16, rb = ra + 8;
        dinvA[m] = (ra < N) ? rsqrtf((float)g_cnt[ra] + 1.0f) : 0.f;
        dinvB[m] = (rb < N) ? rsqrtf((float)g_cnt[rb] + 1.0f) : 0.f;
    }

#pragma unroll 1
    for (int p = 0; p < 2; p++) {
        {
            const uint4* srcH = (const uint4*)(g_wpk_hi + p * 4096);
            const uint4* srcL = (const uint4*)(g_wpk_lo + p * 4096);
            uint4* dH = (uint4*)sHi;
            uint4* dL = (uint4*)sLo;
#pragma unroll
            for (int q = 0; q < 4; q++) {
                dH[tid + q * 256] = srcH[tid + q * 256];
                dL[tid + q * 256] = srcL[tid + q * 256];
            }
        }
        __syncthreads();

        float acc[2][8][4];
#pragma unroll
        for (int m = 0; m < 2; m++)
#pragma unroll
            for (int nt = 0; nt < 8; nt++)
#pragma unroll
                for (int q = 0; q < 4; q++) acc[m][nt][q] = 0.f;

        int off0 = cq * 8 + r;
        int off1 = (cq + 4) * 8 + r;

#pragma unroll 1
        for (int kc = 0; kc < 8; kc++) {
            int k0 = kc * 16 + cq * 2;
            uint32_t ahi[2][4], alo[2][4];
#pragma unroll
            for (int m = 0; m < 2; m++) {
                int ra = rowA + m * 16;
                int rb = ra + 8;
                bool okA = ra < N, okB = rb < N;
                const float* pa = X + (size_t)ra * 128;
                const float* pb = X + (size_t)rb * 128;
                float2 v0 = okA ? *(const float2*)(pa + k0)     : make_float2(0.f, 0.f);
                float2 v1 = okB ? *(const float2*)(pb + k0)     : make_float2(0.f, 0.f);
                float2 v2 = okA ? *(const float2*)(pa + k0 + 8) : make_float2(0.f, 0.f);
                float2 v3 = okB ? *(const float2*)(pb + k0 + 8) : make_float2(0.f, 0.f);
                split_pack(v0, ahi[m][0], alo[m][0]);
                split_pack(v1, ahi[m][1], alo[m][1]);
                split_pack(v2, ahi[m][2], alo[m][2]);
                split_pack(v3, ahi[m][3], alo[m][3]);
            }
            const uint32_t* bH = sHi + kc * 512;
            const uint32_t* bL = sLo + kc * 512;
#pragma unroll
            for (int nt = 0; nt < 8; nt++) {
                uint32_t bh0 = bH[nt * 64 + off0];
                uint32_t bh1 = bH[nt * 64 + off1];
                uint32_t bl0 = bL[nt * 64 + off0];
                uint32_t bl1 = bL[nt * 64 + off1];
#pragma unroll
                for (int m = 0; m < 2; m++) {
                    mma_bf16(acc[m][nt], ahi[m], bh0, bh1);
                    mma_bf16(acc[m][nt], ahi[m], bl0, bl1);
                    mma_bf16(acc[m][nt], alo[m], bh0, bh1);
                }
            }
        }

#pragma unroll
        for (int m = 0; m < 2; m++) {
            int ra = rowA + m * 16;
            int rb = ra + 8;
            bool okA = ra < N, okB = rb < N;
#pragma unroll
            for (int nt = 0; nt < 8; nt++) {
                int col = p * 64 + nt * 8 + cq * 2;
                if (okA) *(float2*)(g_h + (size_t)ra * 128 + col) =
                    make_float2(acc[m][nt][0] * dinvA[m], acc[m][nt][1] * dinvA[m]);
                if (okB) *(float2*)(g_h + (size_t)rb * 128 + col) =
                    make_float2(acc[m][nt][2] * dinvB[m], acc[m][nt][3] * dinvB[m]);
            }
        }
        __syncthreads();
    }
}

// ---------------- launch 2: fused bucket aggregate + selfloop + bias + ReLU + LN + pool ----------------
__global__ __launch_bounds__(256) void k_fused(const int* __restrict__ batch,
                                               const float* __restrict__ bgcn,
                                               const float* __restrict__ gamma,
                                               const float* __restrict__ beta,
                                               int N) {
    __shared__ float s_sum[128];
    __shared__ int   s_max[128];
    __shared__ int   s_cnt;
    int node0 = blockIdx.x * 8;
    if (node0 >= N) return;
    int tid = threadIdx.x;
    int wid = tid >> 5, lane = tid & 31;

    int lastnode = min(node0 + 7, N - 1);
    int gid0 = batch[node0];
    bool uniform = (gid0 == batch[lastnode]);

    if (tid < 128) { s_sum[tid] = 0.f; s_max[tid] = (int)0x80000000; }
    if (tid == 0) s_cnt = 0;
    __syncthreads();

    int node = node0 + wid;
    if (node < N) {
        int deg = g_cnt[node];
        if (lane == 0) g_cnt[node] = 0;     // restore for next graph replay
        float dn = rsqrtf((float)deg + 1.0f);
        const int* bk = g_bucket + (size_t)node * BSTRIDE;
        float4 acc = *(const float4*)(g_h + (size_t)node * 128 + lane * 4);  // self term
        for (int base = 0; base < deg; base += 32) {
            int j = base + lane;
            int s = (j < deg) ? bk[j] : 0;
            int cnt = min(32, deg - base);
            int t = 0;
            for (; t + 4 <= cnt; t += 4) {
                int s0 = __shfl_sync(0xFFFFFFFFu, s, t);
                int s1 = __shfl_sync(0xFFFFFFFFu, s, t + 1);
                int s2 = __shfl_sync(0xFFFFFFFFu, s, t + 2);
                int s3 = __shfl_sync(0xFFFFFFFFu, s, t + 3);
                float4 a = *(const float4*)(g_h + (size_t)s0 * 128 + lane * 4);
                float4 b = *(const float4*)(g_h + (size_t)s1 * 128 + lane * 4);
                float4 c = *(const float4*)(g_h + (size_t)s2 * 128 + lane * 4);
                float4 d = *(const float4*)(g_h + (size_t)s3 * 128 + lane * 4);
                acc.x += (a.x + b.x) + (c.x + d.x);
                acc.y += (a.y + b.y) + (c.y + d.y);
                acc.z += (a.z + b.z) + (c.z + d.z);
                acc.w += (a.w + b.w) + (c.w + d.w);
            }
            for (; t < cnt; t++) {
                int ss = __shfl_sync(0xFFFFFFFFu, s, t);
                float4 v = *(const float4*)(g_h + (size_t)ss * 128 + lane * 4);
                acc.x += v.x; acc.y += v.y; acc.z += v.z; acc.w += v.w;
            }
        }
        float4 b4 = *(const float4*)(bgcn + lane * 4);
        float v0 = fmaxf(fmaf(acc.x, dn, b4.x), 0.f);
        float v1 = fmaxf(fmaf(acc.y, dn, b4.y), 0.f);
        float v2 = fmaxf(fmaf(acc.z, dn, b4.z), 0.f);
        float v3 = fmaxf(fmaf(acc.w, dn, b4.w), 0.f);

        float s  = v0 + v1 + v2 + v3;
        float sq = v0 * v0 + v1 * v1 + v2 * v2 + v3 * v3;
#pragma unroll
        for (int o = 16; o; o >>= 1) {
            s  += __shfl_xor_sync(0xFFFFFFFFu, s, o);
            sq += __shfl_xor_sync(0xFFFFFFFFu, sq, o);
        }
        float mean = s * (1.f / 128.f);
        float var  = sq * (1.f / 128.f) - mean * mean;
        float inv  = rsqrtf(var + 1e-5f);
        float4 gm = *(const float4*)(gamma + lane * 4);
        float4 bt = *(const float4*)(beta + lane * 4);
        float y0 = fmaf((v0 - mean) * inv, gm.x, bt.x);
        float y1 = fmaf((v1 - mean) * inv, gm.y, bt.y);
        float y2 = fmaf((v2 - mean) * inv, gm.z, bt.z);
        float y3 = fmaf((v3 - mean) * inv, gm.w, bt.w);

        if (uniform) {
            atomicAdd(&s_sum[lane * 4 + 0], y0);
            atomicAdd(&s_sum[lane * 4 + 1], y1);
            atomicAdd(&s_sum[lane * 4 + 2], y2);
            atomicAdd(&s_sum[lane * 4 + 3], y3);
            atomicMax(&s_max[lane * 4 + 0], enc_f(y0));
            atomicMax(&s_max[lane * 4 + 1], enc_f(y1));
            atomicMax(&s_max[lane * 4 + 2], enc_f(y2));
            atomicMax(&s_max[lane * 4 + 3], enc_f(y3));
            if (lane == 0) atomicAdd(&s_cnt, 1);
        } else {
            int gid = batch[node];
            float* pa = g_pool_add + (size_t)gid * 128 + lane * 4;
            atomicAdd(pa + 0, y0); atomicAdd(pa + 1, y1);
            atomicAdd(pa + 2, y2); atomicAdd(pa + 3, y3);
            int* pm = g_pool_max + (size_t)gid * 128 + lane * 4;
            atomicMax(pm + 0, enc_f(y0)); atomicMax(pm + 1, enc_f(y1));
            atomicMax(pm + 2, enc_f(y2)); atomicMax(pm + 3, enc_f(y3));
            if (lane == 0) atomicAdd(&g_count[gid], 1);
        }
    }
    __syncthreads();
    if (uniform && tid < 128) {
        atomicAdd(&g_pool_add[(size_t)gid0 * 128 + tid], s_sum[tid]);
        atomicMax(&g_pool_max[(size_t)gid0 * 128 + tid], s_max[tid]);
    }
    if (uniform && tid == 0 && s_cnt > 0) atomicAdd(&g_count[gid0], s_cnt);
}

// ---------------- launch 3: MLP head, 1024-thread k-parallel (+ pool state restore) ----------------
__global__ __launch_bounds__(1024) void k_mlp(const float* __restrict__ W1, const float* __restrict__ b1,
                                              const float* __restrict__ W2, const float* __restrict__ b2,
                                              const float* __restrict__ W3, const float* __restrict__ b3,
                                              float* __restrict__ out, int G) {
    __shared__ float sg[384];
    __shared__ float s_part[1024];
    __shared__ float s1[128];
    __shared__ float s2[64];
    int gid = blockIdx.x;
    int tid = threadIdx.x;
    int cnt = g_count[gid];
    float c = fmaxf((float)cnt, 1.f);
    if (tid < 128) {
        float add = g_pool_add[(size_t)gid * 128 + tid];
        float mx  = (cnt > 0) ? dec_f(g_pool_max[(size_t)gid * 128 + tid]) : 0.f;
        sg[tid]       = add / c;
        sg[128 + tid] = add;
        sg[256 + tid] = mx;
        g_pool_add[(size_t)gid * 128 + tid] = 0.f;
        g_pool_max[(size_t)gid * 128 + tid] = (int)0x80000000;
    }
    if (tid == 0) g_count[gid] = 0;
    __syncthreads();

    // ---- layer 1: 384 -> 128, 8-way k split, 4 accumulators ----
    {
        int o = tid & 127;
        int q = tid >> 7;            // 0..7
        int k0 = q * 48;
        float a0 = 0.f, a1 = 0.f, a2 = 0.f, a3 = 0.f;
        const float* w = W1 + o;
#pragma unroll
        for (int k = k0; k < k0 + 48; k += 4) {
            a0 = fmaf(sg[k + 0], w[(size_t)(k + 0) * 128], a0);
            a1 = fmaf(sg[k + 1], w[(size_t)(k + 1) * 128], a1);
            a2 = fmaf(sg[k + 2], w[(size_t)(k + 2) * 128], a2);
            a3 = fmaf(sg[k + 3], w[(size_t)(k + 3) * 128], a3);
        }
        s_part[tid] = (a0 + a1) + (a2 + a3);
    }
    __syncthreads();
    if (tid < 128) {
        float v = b1[tid];
#pragma unroll
        for (int q = 0; q < 8; q++) v += s_part[tid + q * 128];
        s1[tid] = fmaxf(v, 0.f);
    }
    __syncthreads();

    // ---- layer 2: 128 -> 64, 16-way k split ----
    {
        int o = tid & 63;
        int q = tid >> 6;            // 0..15
        int k0 = q * 8;
        float a0 = 0.f, a1 = 0.f;
        const float* w = W2 + o;
#pragma unroll
        for (int k = k0; k < k0 + 8; k += 2) {
            a0 = fmaf(s1[k + 0], w[(size_t)(k + 0) * 64], a0);
            a1 = fmaf(s1[k + 1], w[(size_t)(k + 1) * 64], a1);
        }
        s_part[tid] = a0 + a1;
    }
    __syncthreads();
    if (tid < 64) {
        float v = b2[tid];
#pragma unroll
        for (int q = 0; q < 16; q++) v += s_part[tid + q * 64];
        s2[tid] = fmaxf(v, 0.f);
    }
    __syncthreads();

    // ---- layer 3: 64 -> 10, one warp per output ----
    {
        int w = tid >> 5, lane = tid & 31;
        if (w < 10) {
            float a = s2[lane] * W3[(size_t)lane * 10 + w]
                    + s2[lane + 32] * W3[(size_t)(lane + 32) * 10 + w];
#pragma unroll
            for (int o = 16; o; o >>= 1) a += __shfl_xor_sync(0xFFFFFFFFu, a, o);
            if (lane == 0) out[gid * 10 + w] = a + b3[w];
        }
    }
}

extern "C" void kernel_launch(void* const* d_in, const int* in_sizes, int n_in,
                              void* d_out, int out_size) {
    const float* x     = (const float*)d_in[0];
    const int*   ei    = (const int*)d_in[1];
    const int*   batch = (const int*)d_in[2];
    const float* Wg    = (const float*)d_in[4];
    const float* bg    = (const float*)d_in[5];
    const float* gamma = (const float*)d_in[6];
    const float* beta  = (const float*)d_in[7];
    const float* W1    = (const float*)d_in[8];
    const float* b1    = (const float*)d_in[9];
    const float* W2    = (const float*)d_in[10];
    const float* b2    = (const float*)d_in[11];
    const float* W3    = (const float*)d_in[12];
    const float* b3    = (const float*)d_in[13];
    float* out = (float*)d_out;

    int N = in_sizes[0] / HDIM;
    int E = in_sizes[1] / 2;
    int G = out_size / 10;

    k_scatter_prep<<<(E + 255) / 256, 256>>>(Wg, ei, E, G);
    k_gemm_mma<<<(N + 255) / 256, 256>>>(x, N);
    k_fused<<<(N + 7) / 8, 256>>>(batch, bg, gamma, beta, N);
    k_mlp<<<G, 1024>>>(W1, b1, W2, b2, W3, b3, out, G);
}